// round 1
// baseline (speedup 1.0000x reference)
#include <cuda_runtime.h>
#include <math.h>
#include <stdint.h>

// Problem dims (fixed)
#define BATCH 4
#define SEQ   4096
#define DIM   1024
#define HEADS 16
#define DHEAD 64
#define DFF   4096
#define ROWS  (BATCH*SEQ)   // 16384

// ---------------------------------------------------------------------------
// Scratch (device globals; no runtime allocation allowed)
// ---------------------------------------------------------------------------
__device__ float g_h1 [ROWS*(size_t)DIM];
__device__ float g_q  [ROWS*(size_t)DIM];
__device__ float g_k  [ROWS*(size_t)DIM];
__device__ float g_v  [ROWS*(size_t)DIM];
__device__ float g_ao [ROWS*(size_t)DIM];
__device__ float g_x2 [ROWS*(size_t)DIM];
__device__ float g_h2 [ROWS*(size_t)DIM];
__device__ float g_dot[BATCH*HEADS*(size_t)SEQ];
__device__ float g_act[ROWS*(size_t)DFF];

// ---------------------------------------------------------------------------
// Helpers
// ---------------------------------------------------------------------------
__device__ __forceinline__ unsigned f2tf(float x) {
    unsigned u;
    asm("cvt.rna.tf32.f32 %0, %1;" : "=r"(u) : "f"(x));
    return u;
}

__device__ __forceinline__ float gelu_exact(float x) {
    return 0.5f * x * (1.0f + erff(x * 0.70710678118654752f));
}

// ---------------------------------------------------------------------------
// LayerNorm: one block per row, 256 threads, D=1024
// ---------------------------------------------------------------------------
__global__ __launch_bounds__(256) void ln_kernel(
    const float* __restrict__ x, const float* __restrict__ gam,
    const float* __restrict__ bet, float* __restrict__ out)
{
    const int row = blockIdx.x;
    const float* xr = x + (size_t)row * DIM;
    float v[4];
    float s = 0.f, ss = 0.f;
#pragma unroll
    for (int i = 0; i < 4; i++) {
        v[i] = xr[threadIdx.x + i * 256];
        s += v[i];
        ss += v[i] * v[i];
    }
#pragma unroll
    for (int o = 16; o; o >>= 1) {
        s  += __shfl_xor_sync(0xffffffffu, s, o);
        ss += __shfl_xor_sync(0xffffffffu, ss, o);
    }
    __shared__ float sh1[8], sh2[8];
    const int w = threadIdx.x >> 5, l = threadIdx.x & 31;
    if (l == 0) { sh1[w] = s; sh2[w] = ss; }
    __syncthreads();
    s = 0.f; ss = 0.f;
#pragma unroll
    for (int i = 0; i < 8; i++) { s += sh1[i]; ss += sh2[i]; }
    const float mu   = s * (1.0f / DIM);
    const float var  = ss * (1.0f / DIM) - mu * mu;
    const float rstd = rsqrtf(var + 1e-5f);
    float* outr = out + (size_t)row * DIM;
#pragma unroll
    for (int i = 0; i < 4; i++) {
        int c = threadIdx.x + i * 256;
        outr[c] = (v[i] - mu) * rstd * gam[c] + bet[c];
    }
}

// ---------------------------------------------------------------------------
// Per-position head dot products: dots[b,h,r] = (q[r]·k[r])_h * DH^-0.5
// grid = B*SEQ blocks, 128 threads; thread t covers 8 consecutive channels
// (head = t/8 since 64/8 = 8 threads per head, aligned).
// ---------------------------------------------------------------------------
__global__ __launch_bounds__(128) void dots_kernel(
    const float* __restrict__ q, const float* __restrict__ k,
    float* __restrict__ dots)
{
    const int row = blockIdx.x;            // b*4096 + r
    const int b = row >> 12, r = row & 4095;
    const int t = threadIdx.x;
    const float4* qr = (const float4*)(q + (size_t)row * DIM);
    const float4* kr = (const float4*)(k + (size_t)row * DIM);
    float p = 0.f;
#pragma unroll
    for (int i = 0; i < 2; i++) {
        float4 a = qr[2 * t + i], c = kr[2 * t + i];
        p += a.x * c.x + a.y * c.y + a.z * c.z + a.w * c.w;
    }
#pragma unroll
    for (int o = 4; o; o >>= 1) p += __shfl_xor_sync(0xffffffffu, p, o);
    if ((t & 7) == 0)
        dots[((size_t)(b * HEADS + (t >> 3))) * SEQ + r] = p * 0.125f;
}

// ---------------------------------------------------------------------------
// Softmax over the full sequence for each (b,h) row; in-place. grid=64.
// ---------------------------------------------------------------------------
__global__ __launch_bounds__(1024) void softmax_kernel(float* __restrict__ d)
{
    const int row = blockIdx.x;
    float4* p = (float4*)(d + (size_t)row * SEQ);
    float4 v = p[threadIdx.x];
    float m = fmaxf(fmaxf(v.x, v.y), fmaxf(v.z, v.w));
#pragma unroll
    for (int o = 16; o; o >>= 1) m = fmaxf(m, __shfl_xor_sync(0xffffffffu, m, o));
    __shared__ float sm[32];
    const int w = threadIdx.x >> 5, l = threadIdx.x & 31;
    if (l == 0) sm[w] = m;
    __syncthreads();
    m = sm[0];
#pragma unroll
    for (int i = 1; i < 32; i++) m = fmaxf(m, sm[i]);
    __syncthreads();
    float4 e;
    e.x = expf(v.x - m); e.y = expf(v.y - m);
    e.z = expf(v.z - m); e.w = expf(v.w - m);
    float s = e.x + e.y + e.z + e.w;
#pragma unroll
    for (int o = 16; o; o >>= 1) s += __shfl_xor_sync(0xffffffffu, s, o);
    if (l == 0) sm[w] = s;
    __syncthreads();
    s = 0.f;
#pragma unroll
    for (int i = 0; i < 32; i++) s += sm[i];
    const float inv = 1.0f / s;
    e.x *= inv; e.y *= inv; e.z *= inv; e.w *= inv;
    p[threadIdx.x] = e;
}

// ---------------------------------------------------------------------------
// Gather: attn_out[b, n', c] = att[b, c/64, p(n')] * V[b, p(n'), c]
// where p(n') = (n' % 128)*32 + (n' / 128)  (strided transpose, applied once)
// ---------------------------------------------------------------------------
__global__ __launch_bounds__(256) void gather_kernel(
    const float* __restrict__ v, const float* __restrict__ att,
    float* __restrict__ out)
{
    const int nb = blockIdx.x;             // b*4096 + n'
    const int b = nb >> 12, n = nb & 4095;
    const int pidx = (n & 127) * 32 + (n >> 7);
    const int t = threadIdx.x;             // channel group c = 4t
    const float a = att[((size_t)(b * HEADS + (t >> 4))) * SEQ + pidx];
    const float4 vv =
        ((const float4*)(v + ((size_t)(b << 12) + pidx) * DIM))[t];
    float4 o;
    o.x = a * vv.x; o.y = a * vv.y; o.z = a * vv.z; o.w = a * vv.w;
    ((float4*)(out + (size_t)nb * DIM))[t] = o;
}

// ---------------------------------------------------------------------------
// TF32 tensor-core GEMM: C[M,N] = A[M,K] @ B[K,N]  (+ epilogue)
//  MODE 0: plain store
//  MODE 1: C = acc + res[m,n] + bias[n]
//  MODE 2: C = gelu(acc + bias[n])
// 128x128x32 tiles, 256 threads (8 warps as 2x4, each warp 64x32),
// register prefetch double-buffering, stride-132 smem padding for
// conflict-free mma fragment loads.
// ---------------------------------------------------------------------------
template <int MODE>
__global__ __launch_bounds__(256) void gemm_tf32(
    const float* __restrict__ A, const float* __restrict__ Bm,
    float* __restrict__ C, const float* __restrict__ res,
    const float* __restrict__ bias, int M, int N, int K)
{
    __shared__ unsigned As[32][132];   // [k][m]
    __shared__ unsigned Bs[32][132];   // [k][n]

    const int tid  = threadIdx.x;
    const int m0   = blockIdx.y << 7;
    const int n0   = blockIdx.x << 7;
    const int warp = tid >> 5, lane = tid & 31;
    const int wm = warp >> 2, wn = warp & 3;
    const int g = lane >> 2, t = lane & 3;

    float acc[4][4][4];
#pragma unroll
    for (int i = 0; i < 4; i++)
#pragma unroll
        for (int j = 0; j < 4; j++)
#pragma unroll
            for (int r = 0; r < 4; r++) acc[i][j][r] = 0.f;

    const int arow = tid >> 3, ac4 = tid & 7;    // A staging map
    const int brow = tid >> 5, bc4 = tid & 31;   // B staging map
    float4 ar[4], br[4];
    const int KT = K >> 5;

    // prefetch kt = 0
#pragma unroll
    for (int i = 0; i < 4; i++)
        ar[i] = *(const float4*)(A + (size_t)(m0 + arow + 32 * i) * K + (ac4 << 2));
#pragma unroll
    for (int i = 0; i < 4; i++)
        br[i] = *(const float4*)(Bm + (size_t)(brow + 8 * i) * N + n0 + (bc4 << 2));

    for (int kt = 0; kt < KT; kt++) {
        // stage regs -> smem (A transposed into [k][m])
#pragma unroll
        for (int i = 0; i < 4; i++) {
            const int r = arow + 32 * i;
            As[ac4 * 4 + 0][r] = f2tf(ar[i].x);
            As[ac4 * 4 + 1][r] = f2tf(ar[i].y);
            As[ac4 * 4 + 2][r] = f2tf(ar[i].z);
            As[ac4 * 4 + 3][r] = f2tf(ar[i].w);
        }
#pragma unroll
        for (int i = 0; i < 4; i++) {
            uint4 u;
            u.x = f2tf(br[i].x); u.y = f2tf(br[i].y);
            u.z = f2tf(br[i].z); u.w = f2tf(br[i].w);
            *(uint4*)&Bs[brow + 8 * i][bc4 << 2] = u;
        }
        __syncthreads();

        if (kt + 1 < KT) {
#pragma unroll
            for (int i = 0; i < 4; i++)
                ar[i] = *(const float4*)(A + (size_t)(m0 + arow + 32 * i) * K +
                                         (kt + 1) * 32 + (ac4 << 2));
#pragma unroll
            for (int i = 0; i < 4; i++)
                br[i] = *(const float4*)(Bm + (size_t)((kt + 1) * 32 + brow + 8 * i) * N +
                                         n0 + (bc4 << 2));
        }

        // compute on current tile
#pragma unroll
        for (int kc = 0; kc < 4; kc++) {
            const int k0 = kc << 3;
            unsigned af[4][4];
#pragma unroll
            for (int i = 0; i < 4; i++) {
                const int mb = wm * 64 + i * 16;
                af[i][0] = As[k0 + t    ][mb + g    ];
                af[i][1] = As[k0 + t    ][mb + g + 8];
                af[i][2] = As[k0 + t + 4][mb + g    ];
                af[i][3] = As[k0 + t + 4][mb + g + 8];
            }
#pragma unroll
            for (int j = 0; j < 4; j++) {
                const int nb = wn * 32 + j * 8;
                const unsigned b0 = Bs[k0 + t    ][nb + g];
                const unsigned b1 = Bs[k0 + t + 4][nb + g];
#pragma unroll
                for (int i = 0; i < 4; i++) {
                    asm volatile(
                        "mma.sync.aligned.m16n8k8.row.col.f32.tf32.tf32.f32 "
                        "{%0,%1,%2,%3}, {%4,%5,%6,%7}, {%8,%9}, {%0,%1,%2,%3};"
                        : "+f"(acc[i][j][0]), "+f"(acc[i][j][1]),
                          "+f"(acc[i][j][2]), "+f"(acc[i][j][3])
                        : "r"(af[i][0]), "r"(af[i][1]),
                          "r"(af[i][2]), "r"(af[i][3]),
                          "r"(b0), "r"(b1));
                }
            }
        }
        __syncthreads();
    }

    // epilogue
#pragma unroll
    for (int i = 0; i < 4; i++) {
#pragma unroll
        for (int j = 0; j < 4; j++) {
            const int row = m0 + wm * 64 + i * 16 + g;
            const int col = n0 + wn * 32 + j * 8 + t * 2;
#pragma unroll
            for (int half = 0; half < 2; half++) {
                const int rr = row + half * 8;
                float a = acc[i][j][half * 2 + 0];
                float b = acc[i][j][half * 2 + 1];
                float2 o;
                if (MODE == 0) {
                    o.x = a; o.y = b;
                } else if (MODE == 1) {
                    const float2 rv = *(const float2*)&res[(size_t)rr * N + col];
                    o.x = a + rv.x + bias[col];
                    o.y = b + rv.y + bias[col + 1];
                } else {
                    o.x = gelu_exact(a + bias[col]);
                    o.y = gelu_exact(b + bias[col + 1]);
                }
                *(float2*)&C[(size_t)rr * N + col] = o;
            }
        }
    }
}

// ---------------------------------------------------------------------------
// Launch
// ---------------------------------------------------------------------------
extern "C" void kernel_launch(void* const* d_in, const int* in_sizes, int n_in,
                              void* d_out, int out_size)
{
    const float* x     = (const float*)d_in[0];
    const float* ln1_g = (const float*)d_in[1];
    const float* ln1_b = (const float*)d_in[2];
    const float* wq    = (const float*)d_in[3];
    const float* wk    = (const float*)d_in[4];
    const float* wv    = (const float*)d_in[5];
    const float* wo    = (const float*)d_in[6];
    const float* bo    = (const float*)d_in[7];
    const float* ln2_g = (const float*)d_in[8];
    const float* ln2_b = (const float*)d_in[9];
    const float* w1    = (const float*)d_in[10];
    const float* b1    = (const float*)d_in[11];
    const float* w2    = (const float*)d_in[12];
    const float* b2    = (const float*)d_in[13];
    float* out = (float*)d_out;

    float *h1, *q, *k, *v, *ao, *x2, *h2, *dots, *act;
    cudaGetSymbolAddress((void**)&h1,  g_h1);
    cudaGetSymbolAddress((void**)&q,   g_q);
    cudaGetSymbolAddress((void**)&k,   g_k);
    cudaGetSymbolAddress((void**)&v,   g_v);
    cudaGetSymbolAddress((void**)&ao,  g_ao);
    cudaGetSymbolAddress((void**)&x2,  g_x2);
    cudaGetSymbolAddress((void**)&h2,  g_h2);
    cudaGetSymbolAddress((void**)&dots,g_dot);
    cudaGetSymbolAddress((void**)&act, g_act);

    const dim3 g1024(DIM / 128, ROWS / 128);   // N=1024 GEMMs
    const dim3 g4096(DFF / 128, ROWS / 128);   // N=4096 GEMM

    // 1. h1 = LN1(x)
    ln_kernel<<<ROWS, 256>>>(x, ln1_g, ln1_b, h1);
    // 2-4. Q,K,V = h1 @ {wq,wk,wv}
    gemm_tf32<0><<<g1024, 256>>>(h1, wq, q, nullptr, nullptr, ROWS, DIM, DIM);
    gemm_tf32<0><<<g1024, 256>>>(h1, wk, k, nullptr, nullptr, ROWS, DIM, DIM);
    gemm_tf32<0><<<g1024, 256>>>(h1, wv, v, nullptr, nullptr, ROWS, DIM, DIM);
    // 5. per-position head dots (original row order; softmax is perm-invariant)
    dots_kernel<<<ROWS, 128>>>(q, k, dots);
    // 6. softmax over full sequence per (b,h)
    softmax_kernel<<<BATCH * HEADS, 1024>>>(dots);
    // 7. gather: apply strided transpose + att*V
    gather_kernel<<<ROWS, 256>>>(v, dots, ao);
    // 8. x2 = x + ao @ wo + bo
    gemm_tf32<1><<<g1024, 256>>>(ao, wo, x2, x, bo, ROWS, DIM, DIM);
    // 9. h2 = LN2(x2)
    ln_kernel<<<ROWS, 256>>>(x2, ln2_g, ln2_b, h2);
    // 10. act = gelu(h2 @ w1 + b1)
    gemm_tf32<2><<<g4096, 256>>>(h2, w1, act, nullptr, b1, ROWS, DFF, DIM);
    // 11. out = x2 + act @ w2 + b2
    gemm_tf32<1><<<g1024, 256>>>(act, w2, out, x2, b2, ROWS, DIM, DFF);
}

// round 3
// speedup vs baseline: 1.6898x; 1.6898x over previous
#include <cuda_runtime.h>
#include <math.h>
#include <stdint.h>

// Problem dims (fixed)
#define BATCH 4
#define SEQ   4096
#define DIM   1024
#define HEADS 16
#define DFF   4096
#define ROWS  16384
#define QKVW  3072

// ---------------------------------------------------------------------------
// Scratch (device globals; no runtime allocation allowed)
// ---------------------------------------------------------------------------
__device__ float g_h1  [ROWS*(size_t)DIM];
__device__ float g_qkv [ROWS*(size_t)QKVW];
__device__ float g_ao  [ROWS*(size_t)DIM];
__device__ float g_x2  [ROWS*(size_t)DIM];
__device__ float g_h2  [ROWS*(size_t)DIM];
__device__ float g_dot [BATCH*HEADS*(size_t)SEQ];
__device__ float g_act [ROWS*(size_t)DFF];
__device__ float g_wqkvT[(size_t)QKVW*DIM];   // [3072][1024]  K-major (N rows)
__device__ float g_woT [(size_t)DIM*DIM];
__device__ float g_w1T [(size_t)DFF*DIM];
__device__ float g_w2T [(size_t)DIM*DFF];

// ---------------------------------------------------------------------------
// Helpers
// ---------------------------------------------------------------------------
__device__ __forceinline__ float rna(float x) {
    uint32_t u; asm("cvt.rna.tf32.f32 %0, %1;" : "=r"(u) : "f"(x));
    return __uint_as_float(u);
}
__device__ __forceinline__ float gelu_exact(float x) {
    return 0.5f * x * (1.0f + erff(x * 0.70710678118654752f));
}
__device__ __forceinline__ uint32_t smem_u32(const void* p) {
    uint32_t a;
    asm("{ .reg .u64 t; cvta.to.shared.u64 t, %1; cvt.u32.u64 %0, t; }"
        : "=r"(a) : "l"(p));
    return a;
}
__device__ __forceinline__ void cp16(uint32_t dst, const void* src) {
    asm volatile("cp.async.cg.shared.global [%0], [%1], 16;" :: "r"(dst), "l"(src));
}
__device__ __forceinline__ void cp_commit() {
    asm volatile("cp.async.commit_group;" ::: "memory");
}

// smem row stride in words: 32 k-values + 4 pad -> bank = (4g+t) conflict-free
#define RS       36
#define OPW      (128*RS)                 // words per operand tile (4608)
#define STAGE_W  (2*OPW)                  // words per stage (9216)
#define STAGE_B  (STAGE_W*4)              // 36864 bytes
#define STAGES   3
#define SMEM_DYN (STAGES*STAGE_B)         // 110592

// ---------------------------------------------------------------------------
// TF32 tensor-core GEMM: C[M,N] = A[M,K] @ Bt[N,K]^T   (A,Bt tf32-prerounded)
//  EPI 0: plain   EPI 1: +res+bias   EPI 2: rna(gelu(+bias))
// CTA 128x128, 128 threads (4 warps as 2x2, warp tile 64x64), k-chunk 32,
// 3-stage cp.async pipeline, conflict-free stride-36 smem.
// ---------------------------------------------------------------------------
template <int EPI>
__global__ __launch_bounds__(128, 2) void gemm_tc(
    const float* __restrict__ A, const float* __restrict__ Bt,
    float* __restrict__ C, const float* __restrict__ res,
    const float* __restrict__ bias, int M, int N, int K)
{
    extern __shared__ float sm[];
    const uint32_t smb = smem_u32(sm);

    const int tid  = threadIdx.x;
    const int lane = tid & 31;
    const int wid  = tid >> 5;
    const int wm   = wid >> 1;       // warp m index (0..1)
    const int wn   = wid & 1;        // warp n index (0..1)
    const int g    = lane >> 2;      // group-of-4 row (0..7)
    const int t    = lane & 3;       // thread in group (0..3)
    const int m0   = blockIdx.y << 7;
    const int n0   = blockIdx.x << 7;

    // staging maps: granule j -> gid = j*128+tid ; row = gid>>3 ; c = gid&7
    uint32_t sA[8], sB[8];
    const float* gA[8];
    const float* gB[8];
#pragma unroll
    for (int j = 0; j < 8; j++) {
        const int gid = j * 128 + tid;
        const int row = gid >> 3, c = gid & 7;
        sA[j] = (uint32_t)(row * RS + c * 4) * 4u;
        sB[j] = (uint32_t)(OPW + row * RS + c * 4) * 4u;
        gA[j] = A  + (size_t)(m0 + row) * K + c * 4;
        gB[j] = Bt + (size_t)(n0 + row) * K + c * 4;
    }

    float acc[4][8][4];
#pragma unroll
    for (int i = 0; i < 4; i++)
#pragma unroll
        for (int j = 0; j < 8; j++)
#pragma unroll
            for (int r = 0; r < 4; r++) acc[i][j][r] = 0.f;

    const int KT = K >> 5;

    // prologue: stages 0..2
#pragma unroll
    for (int s = 0; s < STAGES; s++) {
        const uint32_t base = smb + s * STAGE_B;
        const int ko = s * 32;
#pragma unroll
        for (int j = 0; j < 8; j++) {
            cp16(base + sA[j], gA[j] + ko);
            cp16(base + sB[j], gB[j] + ko);
        }
        cp_commit();
    }

    for (int kt = 0; kt < KT; kt++) {
        asm volatile("cp.async.wait_group 2;" ::: "memory");
        __syncthreads();

        const float* As = sm + (kt % STAGES) * STAGE_W;
        const float* Bs = As + OPW;

#pragma unroll
        for (int kc = 0; kc < 4; kc++) {
            const int k0 = kc << 3;
            uint32_t af[4][4];
#pragma unroll
            for (int i = 0; i < 4; i++) {
                const int mb = wm * 64 + i * 16;
                af[i][0] = __float_as_uint(As[(mb + g    ) * RS + k0 + t    ]);
                af[i][1] = __float_as_uint(As[(mb + g + 8) * RS + k0 + t    ]);
                af[i][2] = __float_as_uint(As[(mb + g    ) * RS + k0 + t + 4]);
                af[i][3] = __float_as_uint(As[(mb + g + 8) * RS + k0 + t + 4]);
            }
            uint32_t bf[8][2];
#pragma unroll
            for (int j = 0; j < 8; j++) {
                const int nb = wn * 64 + j * 8;
                bf[j][0] = __float_as_uint(Bs[(nb + g) * RS + k0 + t    ]);
                bf[j][1] = __float_as_uint(Bs[(nb + g) * RS + k0 + t + 4]);
            }
#pragma unroll
            for (int i = 0; i < 4; i++)
#pragma unroll
                for (int j = 0; j < 8; j++) {
                    asm volatile(
                        "mma.sync.aligned.m16n8k8.row.col.f32.tf32.tf32.f32 "
                        "{%0,%1,%2,%3}, {%4,%5,%6,%7}, {%8,%9}, {%0,%1,%2,%3};"
                        : "+f"(acc[i][j][0]), "+f"(acc[i][j][1]),
                          "+f"(acc[i][j][2]), "+f"(acc[i][j][3])
                        : "r"(af[i][0]), "r"(af[i][1]),
                          "r"(af[i][2]), "r"(af[i][3]),
                          "r"(bf[j][0]), "r"(bf[j][1]));
                }
        }
        __syncthreads();

        const int nk = kt + STAGES;
        if (nk < KT) {
            const uint32_t base = smb + (nk % STAGES) * STAGE_B;
            const int ko = nk * 32;
#pragma unroll
            for (int j = 0; j < 8; j++) {
                cp16(base + sA[j], gA[j] + ko);
                cp16(base + sB[j], gB[j] + ko);
            }
        }
        cp_commit();
    }

    // epilogue: direct float2 stores from accumulators
#pragma unroll
    for (int j = 0; j < 8; j++) {
        const int col = n0 + wn * 64 + j * 8 + t * 2;
        float2 bv = make_float2(0.f, 0.f);
        if (EPI != 0) bv = *(const float2*)&bias[col];
#pragma unroll
        for (int i = 0; i < 4; i++) {
            const int row0 = m0 + wm * 64 + i * 16 + g;
#pragma unroll
            for (int h = 0; h < 2; h++) {
                const int r = row0 + 8 * h;
                float a = acc[i][j][2 * h + 0];
                float b = acc[i][j][2 * h + 1];
                float2 o;
                if (EPI == 0) {
                    o.x = a; o.y = b;
                } else if (EPI == 1) {
                    const float2 rv = *(const float2*)&res[(size_t)r * N + col];
                    o.x = a + rv.x + bv.x;
                    o.y = b + rv.y + bv.y;
                } else {
                    o.x = rna(gelu_exact(a + bv.x));
                    o.y = rna(gelu_exact(b + bv.y));
                }
                *(float2*)&C[(size_t)r * N + col] = o;
            }
        }
    }
}

// ---------------------------------------------------------------------------
// Weight transpose: in [R][C] -> out [C][R], rounded to tf32 (RNA)
// ---------------------------------------------------------------------------
__global__ __launch_bounds__(256) void transpose_k(
    const float* __restrict__ in, float* __restrict__ out, int R, int C)
{
    __shared__ float t[32][33];
    const int c0 = blockIdx.x * 32, r0 = blockIdx.y * 32;
    const int tx = threadIdx.x, ty = threadIdx.y;
#pragma unroll
    for (int j = 0; j < 4; j++)
        t[ty + j * 8][tx] = in[(size_t)(r0 + ty + j * 8) * C + c0 + tx];
    __syncthreads();
#pragma unroll
    for (int j = 0; j < 4; j++)
        out[(size_t)(c0 + ty + j * 8) * R + r0 + tx] = rna(t[tx][ty + j * 8]);
}

// ---------------------------------------------------------------------------
// LayerNorm (output rounded to tf32 — it feeds a GEMM A operand)
// ---------------------------------------------------------------------------
__global__ __launch_bounds__(256) void ln_kernel(
    const float* __restrict__ x, const float* __restrict__ gam,
    const float* __restrict__ bet, float* __restrict__ out)
{
    const int row = blockIdx.x;
    const float* xr = x + (size_t)row * DIM;
    float v[4];
    float s = 0.f, ss = 0.f;
#pragma unroll
    for (int i = 0; i < 4; i++) {
        v[i] = xr[threadIdx.x + i * 256];
        s += v[i]; ss += v[i] * v[i];
    }
#pragma unroll
    for (int o = 16; o; o >>= 1) {
        s  += __shfl_xor_sync(0xffffffffu, s, o);
        ss += __shfl_xor_sync(0xffffffffu, ss, o);
    }
    __shared__ float sh1[8], sh2[8];
    const int w = threadIdx.x >> 5, l = threadIdx.x & 31;
    if (l == 0) { sh1[w] = s; sh2[w] = ss; }
    __syncthreads();
    s = 0.f; ss = 0.f;
#pragma unroll
    for (int i = 0; i < 8; i++) { s += sh1[i]; ss += sh2[i]; }
    const float mu   = s * (1.0f / DIM);
    const float var  = ss * (1.0f / DIM) - mu * mu;
    const float rstd = rsqrtf(var + 1e-5f);
    float* outr = out + (size_t)row * DIM;
#pragma unroll
    for (int i = 0; i < 4; i++) {
        int c = threadIdx.x + i * 256;
        outr[c] = rna((v[i] - mu) * rstd * gam[c] + bet[c]);
    }
}

// ---------------------------------------------------------------------------
// Per-position head dots from combined qkv buffer
// ---------------------------------------------------------------------------
__global__ __launch_bounds__(128) void dots_kernel(
    const float* __restrict__ qkv, float* __restrict__ dots)
{
    const int row = blockIdx.x;
    const int b = row >> 12, r = row & 4095;
    const int t = threadIdx.x;
    const float4* qr = (const float4*)(qkv + (size_t)row * QKVW);
    const float4* kr = (const float4*)(qkv + (size_t)row * QKVW + DIM);
    float p = 0.f;
#pragma unroll
    for (int i = 0; i < 2; i++) {
        float4 a = qr[2 * t + i], c = kr[2 * t + i];
        p += a.x * c.x + a.y * c.y + a.z * c.z + a.w * c.w;
    }
#pragma unroll
    for (int o = 4; o; o >>= 1) p += __shfl_xor_sync(0xffffffffu, p, o);
    if ((t & 7) == 0)
        dots[((size_t)(b * HEADS + (t >> 3))) * SEQ + r] = p * 0.125f;
}

__global__ __launch_bounds__(1024) void softmax_kernel(float* __restrict__ d)
{
    const int row = blockIdx.x;
    float4* p = (float4*)(d + (size_t)row * SEQ);
    float4 v = p[threadIdx.x];
    float m = fmaxf(fmaxf(v.x, v.y), fmaxf(v.z, v.w));
#pragma unroll
    for (int o = 16; o; o >>= 1) m = fmaxf(m, __shfl_xor_sync(0xffffffffu, m, o));
    __shared__ float sm[32];
    const int w = threadIdx.x >> 5, l = threadIdx.x & 31;
    if (l == 0) sm[w] = m;
    __syncthreads();
    m = sm[0];
#pragma unroll
    for (int i = 1; i < 32; i++) m = fmaxf(m, sm[i]);
    __syncthreads();
    float4 e;
    e.x = expf(v.x - m); e.y = expf(v.y - m);
    e.z = expf(v.z - m); e.w = expf(v.w - m);
    float s = e.x + e.y + e.z + e.w;
#pragma unroll
    for (int o = 16; o; o >>= 1) s += __shfl_xor_sync(0xffffffffu, s, o);
    if (l == 0) sm[w] = s;
    __syncthreads();
    s = 0.f;
#pragma unroll
    for (int i = 0; i < 32; i++) s += sm[i];
    const float inv = 1.0f / s;
    e.x *= inv; e.y *= inv; e.z *= inv; e.w *= inv;
    p[threadIdx.x] = e;
}

// attn_out[b,n',c] = att[b, c/64, p(n')] * V[b, p(n'), c]; p(n')=(n'%128)*32+n'/128
__global__ __launch_bounds__(256) void gather_kernel(
    const float* __restrict__ qkv, const float* __restrict__ att,
    float* __restrict__ out)
{
    const int nb = blockIdx.x;
    const int b = nb >> 12, n = nb & 4095;
    const int pidx = (n & 127) * 32 + (n >> 7);
    const int t = threadIdx.x;
    const float a = att[((size_t)(b * HEADS + (t >> 4))) * SEQ + pidx];
    const float4 vv =
        ((const float4*)(qkv + ((size_t)((b << 12) + pidx)) * QKVW + 2 * DIM))[t];
    float4 o;
    o.x = rna(a * vv.x); o.y = rna(a * vv.y);
    o.z = rna(a * vv.z); o.w = rna(a * vv.w);
    ((float4*)(out + (size_t)nb * DIM))[t] = o;
}

// ---------------------------------------------------------------------------
// Launch
// ---------------------------------------------------------------------------
extern "C" void kernel_launch(void* const* d_in, const int* in_sizes, int n_in,
                              void* d_out, int out_size)
{
    const float* x     = (const float*)d_in[0];
    const float* ln1_g = (const float*)d_in[1];
    const float* ln1_b = (const float*)d_in[2];
    const float* wq    = (const float*)d_in[3];
    const float* wk    = (const float*)d_in[4];
    const float* wv    = (const float*)d_in[5];
    const float* wo    = (const float*)d_in[6];
    const float* bo    = (const float*)d_in[7];
    const float* ln2_g = (const float*)d_in[8];
    const float* ln2_b = (const float*)d_in[9];
    const float* w1    = (const float*)d_in[10];
    const float* b1    = (const float*)d_in[11];
    const float* w2    = (const float*)d_in[12];
    const float* b2    = (const float*)d_in[13];
    float* out = (float*)d_out;

    float *h1, *qkv, *ao, *x2, *h2, *dots, *act, *wqkvT, *woT, *w1T, *w2T;
    cudaGetSymbolAddress((void**)&h1,   g_h1);
    cudaGetSymbolAddress((void**)&qkv,  g_qkv);
    cudaGetSymbolAddress((void**)&ao,   g_ao);
    cudaGetSymbolAddress((void**)&x2,   g_x2);
    cudaGetSymbolAddress((void**)&h2,   g_h2);
    cudaGetSymbolAddress((void**)&dots, g_dot);
    cudaGetSymbolAddress((void**)&act,  g_act);
    cudaGetSymbolAddress((void**)&wqkvT,g_wqkvT);
    cudaGetSymbolAddress((void**)&woT,  g_woT);
    cudaGetSymbolAddress((void**)&w1T,  g_w1T);
    cudaGetSymbolAddress((void**)&w2T,  g_w2T);

    cudaFuncSetAttribute(gemm_tc<0>, cudaFuncAttributeMaxDynamicSharedMemorySize, SMEM_DYN);
    cudaFuncSetAttribute(gemm_tc<1>, cudaFuncAttributeMaxDynamicSharedMemorySize, SMEM_DYN);
    cudaFuncSetAttribute(gemm_tc<2>, cudaFuncAttributeMaxDynamicSharedMemorySize, SMEM_DYN);

    const dim3 tb(32, 8);
    // weight transposes (K-major B operands), rounded to tf32
    transpose_k<<<dim3(32, 32), tb>>>(wq, wqkvT,                     DIM, DIM);
    transpose_k<<<dim3(32, 32), tb>>>(wk, wqkvT + (size_t)DIM*DIM,   DIM, DIM);
    transpose_k<<<dim3(32, 32), tb>>>(wv, wqkvT + (size_t)2*DIM*DIM, DIM, DIM);
    transpose_k<<<dim3(32, 32), tb>>>(wo, woT, DIM, DIM);
    transpose_k<<<dim3(128, 32), tb>>>(w1, w1T, DIM, DFF);
    transpose_k<<<dim3(32, 128), tb>>>(w2, w2T, DFF, DIM);

    // 1. h1 = LN1(x)   (tf32-rounded)
    ln_kernel<<<ROWS, 256>>>(x, ln1_g, ln1_b, h1);
    // 2. qkv = h1 @ [wq|wk|wv]
    gemm_tc<0><<<dim3(QKVW/128, ROWS/128), 128, SMEM_DYN>>>(
        h1, wqkvT, qkv, nullptr, nullptr, ROWS, QKVW, DIM);
    // 3-5. diagonal dots -> softmax over sequence -> permuted gather * V
    dots_kernel<<<ROWS, 128>>>(qkv, dots);
    softmax_kernel<<<BATCH * HEADS, 1024>>>(dots);
    gather_kernel<<<ROWS, 256>>>(qkv, dots, ao);
    // 6. x2 = x + ao @ wo + bo
    gemm_tc<1><<<dim3(DIM/128, ROWS/128), 128, SMEM_DYN>>>(
        ao, woT, x2, x, bo, ROWS, DIM, DIM);
    // 7. h2 = LN2(x2)
    ln_kernel<<<ROWS, 256>>>(x2, ln2_g, ln2_b, h2);
    // 8. act = gelu(h2 @ w1 + b1)   (tf32-rounded)
    gemm_tc<2><<<dim3(DFF/128, ROWS/128), 128, SMEM_DYN>>>(
        h2, w1T, act, nullptr, b1, ROWS, DFF, DIM);
    // 9. out = x2 + act @ w2 + b2
    gemm_tc<1><<<dim3(DIM/128, ROWS/128), 128, SMEM_DYN>>>(
        act, w2T, out, x2, b2, ROWS, DIM, DFF);
}

// round 4
// speedup vs baseline: 2.7635x; 1.6355x over previous
#include <cuda_runtime.h>
#include <cuda_fp16.h>
#include <math.h>
#include <stdint.h>

// Problem dims (fixed)
#define BATCH 4
#define SEQ   4096
#define DIM   1024
#define HEADS 16
#define DFF   4096
#define ROWS  16384
#define QKVW  3072

// ---------------------------------------------------------------------------
// Scratch (device globals; no runtime allocation allowed)
// ---------------------------------------------------------------------------
__device__ __half g_h1  [ROWS*(size_t)DIM];
__device__ __half g_qkv [ROWS*(size_t)QKVW];
__device__ __half g_ao  [ROWS*(size_t)DIM];
__device__ float  g_x2  [ROWS*(size_t)DIM];
__device__ __half g_h2  [ROWS*(size_t)DIM];
__device__ float  g_dot [BATCH*HEADS*(size_t)SEQ];
__device__ __half g_act [ROWS*(size_t)DFF];
__device__ __half g_wqkvT[(size_t)QKVW*DIM];   // [3072][1024] K-major (N rows)
__device__ __half g_woT [(size_t)DIM*DIM];
__device__ __half g_w1T [(size_t)DFF*DIM];
__device__ __half g_w2T [(size_t)DIM*DFF];

// ---------------------------------------------------------------------------
// Helpers
// ---------------------------------------------------------------------------
__device__ __forceinline__ float gelu_exact(float x) {
    return 0.5f * x * (1.0f + erff(x * 0.70710678118654752f));
}
__device__ __forceinline__ uint32_t smem_u32(const void* p) {
    uint32_t a;
    asm("{ .reg .u64 t; cvta.to.shared.u64 t, %1; cvt.u32.u64 %0, t; }"
        : "=r"(a) : "l"(p));
    return a;
}
__device__ __forceinline__ void cp16(uint32_t dst, const void* src) {
    asm volatile("cp.async.cg.shared.global [%0], [%1], 16;" :: "r"(dst), "l"(src));
}
__device__ __forceinline__ void cp_commit() {
    asm volatile("cp.async.commit_group;" ::: "memory");
}

// smem row: 32 k-halves data + 8 pad halves -> stride 40 halves (20 words, 80B)
// fragment .b32 load bank = (g*20 + t) mod 32 : all 32 lanes distinct.
#define RSW      20                        // row stride in words
#define OP_B     10240                     // bytes per operand tile (128*80)
#define STAGE_B  (2*OP_B)                  // 20480
#define STAGES   3
#define SMEM_DYN (STAGES*STAGE_B)          // 61440

// ---------------------------------------------------------------------------
// FP16 tensor-core GEMM: C[M,N] = A[M,K] @ Bt[N,K]^T  (A,Bt fp16)
//  EPI 0: store half           (C = __half*)
//  EPI 1: float store +res+bias (C = float*, res fp32)
//  EPI 2: half store gelu(+bias)
// CTA 128x128, 128 threads (4 warps 2x2, warp tile 64x64), k-chunk 32,
// 3-stage cp.async pipeline.
// ---------------------------------------------------------------------------
template <int EPI>
__global__ __launch_bounds__(128, 2) void gemm_fp16(
    const __half* __restrict__ A, const __half* __restrict__ Bt,
    void* __restrict__ Cv, const float* __restrict__ res,
    const float* __restrict__ bias, int M, int N, int K)
{
    extern __shared__ float smf[];
    const uint32_t smb = smem_u32(smf);
    const uint32_t* smw = (const uint32_t*)smf;

    const int tid  = threadIdx.x;
    const int lane = tid & 31;
    const int wid  = tid >> 5;
    const int wm   = wid >> 1;
    const int wn   = wid & 1;
    const int g    = lane >> 2;
    const int t    = lane & 3;
    const int m0   = blockIdx.y << 7;
    const int n0   = blockIdx.x << 7;

    // staging: per operand 512 granules of 16B; 4 per thread
    uint32_t sA[4], sB[4];
    const __half* gA[4];
    const __half* gB[4];
#pragma unroll
    for (int j = 0; j < 4; j++) {
        const int gid = j * 128 + tid;
        const int row = gid >> 2, c = gid & 3;
        sA[j] = (uint32_t)(row * 80 + c * 16);
        sB[j] = (uint32_t)(OP_B + row * 80 + c * 16);
        gA[j] = A  + (size_t)(m0 + row) * K + c * 8;
        gB[j] = Bt + (size_t)(n0 + row) * K + c * 8;
    }

    float acc[4][8][4];
#pragma unroll
    for (int i = 0; i < 4; i++)
#pragma unroll
        for (int j = 0; j < 8; j++)
#pragma unroll
            for (int r = 0; r < 4; r++) acc[i][j][r] = 0.f;

    const int KT = K >> 5;

#pragma unroll
    for (int s = 0; s < STAGES; s++) {
        const uint32_t base = smb + s * STAGE_B;
        const int ko = s * 32;
#pragma unroll
        for (int j = 0; j < 4; j++) {
            cp16(base + sA[j], gA[j] + ko);
            cp16(base + sB[j], gB[j] + ko);
        }
        cp_commit();
    }

    for (int kt = 0; kt < KT; kt++) {
        asm volatile("cp.async.wait_group 2;" ::: "memory");
        __syncthreads();

        const uint32_t* As = smw + (kt % STAGES) * (STAGE_B / 4);
        const uint32_t* Bs = As + OP_B / 4;

#pragma unroll
        for (int kc = 0; kc < 2; kc++) {
            const int k0 = kc << 3;                    // word offset
            uint32_t af[4][4];
#pragma unroll
            for (int i = 0; i < 4; i++) {
                const int mb = wm * 64 + i * 16;
                af[i][0] = As[(mb + g    ) * RSW + k0 + t    ];
                af[i][1] = As[(mb + g + 8) * RSW + k0 + t    ];
                af[i][2] = As[(mb + g    ) * RSW + k0 + t + 4];
                af[i][3] = As[(mb + g + 8) * RSW + k0 + t + 4];
            }
            uint32_t bf[8][2];
#pragma unroll
            for (int j = 0; j < 8; j++) {
                const int nb = wn * 64 + j * 8;
                bf[j][0] = Bs[(nb + g) * RSW + k0 + t    ];
                bf[j][1] = Bs[(nb + g) * RSW + k0 + t + 4];
            }
#pragma unroll
            for (int i = 0; i < 4; i++)
#pragma unroll
                for (int j = 0; j < 8; j++) {
                    asm volatile(
                        "mma.sync.aligned.m16n8k16.row.col.f32.f16.f16.f32 "
                        "{%0,%1,%2,%3}, {%4,%5,%6,%7}, {%8,%9}, {%0,%1,%2,%3};"
                        : "+f"(acc[i][j][0]), "+f"(acc[i][j][1]),
                          "+f"(acc[i][j][2]), "+f"(acc[i][j][3])
                        : "r"(af[i][0]), "r"(af[i][1]),
                          "r"(af[i][2]), "r"(af[i][3]),
                          "r"(bf[j][0]), "r"(bf[j][1]));
                }
        }
        __syncthreads();

        const int nk = kt + STAGES;
        if (nk < KT) {
            const uint32_t base = smb + (nk % STAGES) * STAGE_B;
            const int ko = nk * 32;
#pragma unroll
            for (int j = 0; j < 4; j++) {
                cp16(base + sA[j], gA[j] + ko);
                cp16(base + sB[j], gB[j] + ko);
            }
        }
        cp_commit();
    }

    // epilogue
#pragma unroll
    for (int j = 0; j < 8; j++) {
        const int col = n0 + wn * 64 + j * 8 + t * 2;
        float2 bv = make_float2(0.f, 0.f);
        if (EPI != 0) bv = *(const float2*)&bias[col];
#pragma unroll
        for (int i = 0; i < 4; i++) {
            const int row0 = m0 + wm * 64 + i * 16 + g;
#pragma unroll
            for (int h = 0; h < 2; h++) {
                const int r = row0 + 8 * h;
                const float a = acc[i][j][2 * h + 0];
                const float b = acc[i][j][2 * h + 1];
                if (EPI == 0) {
                    *(__half2*)((__half*)Cv + (size_t)r * N + col) =
                        __floats2half2_rn(a, b);
                } else if (EPI == 1) {
                    const float2 rv = *(const float2*)&res[(size_t)r * N + col];
                    float2 o;
                    o.x = a + rv.x + bv.x;
                    o.y = b + rv.y + bv.y;
                    *(float2*)((float*)Cv + (size_t)r * N + col) = o;
                } else {
                    *(__half2*)((__half*)Cv + (size_t)r * N + col) =
                        __floats2half2_rn(gelu_exact(a + bv.x),
                                          gelu_exact(b + bv.y));
                }
            }
        }
    }
}

// ---------------------------------------------------------------------------
// Weight transpose: in fp32 [R][C] -> out fp16 [C][R]
// ---------------------------------------------------------------------------
__global__ __launch_bounds__(256) void transpose_k(
    const float* __restrict__ in, __half* __restrict__ out, int R, int C)
{
    __shared__ float t[32][33];
    const int c0 = blockIdx.x * 32, r0 = blockIdx.y * 32;
    const int tx = threadIdx.x, ty = threadIdx.y;
#pragma unroll
    for (int j = 0; j < 4; j++)
        t[ty + j * 8][tx] = in[(size_t)(r0 + ty + j * 8) * C + c0 + tx];
    __syncthreads();
#pragma unroll
    for (int j = 0; j < 4; j++)
        out[(size_t)(c0 + ty + j * 8) * R + r0 + tx] = __float2half(t[tx][ty + j * 8]);
}

// ---------------------------------------------------------------------------
// LayerNorm -> fp16 output (feeds GEMM A)
// ---------------------------------------------------------------------------
__global__ __launch_bounds__(256) void ln_kernel(
    const float* __restrict__ x, const float* __restrict__ gam,
    const float* __restrict__ bet, __half* __restrict__ out)
{
    const int row = blockIdx.x;
    const float* xr = x + (size_t)row * DIM;
    float v[4];
    float s = 0.f, ss = 0.f;
#pragma unroll
    for (int i = 0; i < 4; i++) {
        v[i] = xr[threadIdx.x + i * 256];
        s += v[i]; ss += v[i] * v[i];
    }
#pragma unroll
    for (int o = 16; o; o >>= 1) {
        s  += __shfl_xor_sync(0xffffffffu, s, o);
        ss += __shfl_xor_sync(0xffffffffu, ss, o);
    }
    __shared__ float sh1[8], sh2[8];
    const int w = threadIdx.x >> 5, l = threadIdx.x & 31;
    if (l == 0) { sh1[w] = s; sh2[w] = ss; }
    __syncthreads();
    s = 0.f; ss = 0.f;
#pragma unroll
    for (int i = 0; i < 8; i++) { s += sh1[i]; ss += sh2[i]; }
    const float mu   = s * (1.0f / DIM);
    const float var  = ss * (1.0f / DIM) - mu * mu;
    const float rstd = rsqrtf(var + 1e-5f);
    __half* outr = out + (size_t)row * DIM;
#pragma unroll
    for (int i = 0; i < 4; i++) {
        int c = threadIdx.x + i * 256;
        outr[c] = __float2half((v[i] - mu) * rstd * gam[c] + bet[c]);
    }
}

// ---------------------------------------------------------------------------
// Per-position head dots from fp16 qkv: thread t covers 8 channels
// ---------------------------------------------------------------------------
__global__ __launch_bounds__(128) void dots_kernel(
    const __half* __restrict__ qkv, float* __restrict__ dots)
{
    const int row = blockIdx.x;
    const int b = row >> 12, r = row & 4095;
    const int t = threadIdx.x;
    const __half2* qr = (const __half2*)(qkv + (size_t)row * QKVW + 8 * t);
    const __half2* kr = (const __half2*)(qkv + (size_t)row * QKVW + DIM + 8 * t);
    float p = 0.f;
#pragma unroll
    for (int i = 0; i < 4; i++) {
        const float2 a = __half22float2(qr[i]);
        const float2 c = __half22float2(kr[i]);
        p += a.x * c.x + a.y * c.y;
    }
#pragma unroll
    for (int o = 4; o; o >>= 1) p += __shfl_xor_sync(0xffffffffu, p, o);
    if ((t & 7) == 0)
        dots[((size_t)(b * HEADS + (t >> 3))) * SEQ + r] = p * 0.125f;
}

__global__ __launch_bounds__(1024) void softmax_kernel(float* __restrict__ d)
{
    const int row = blockIdx.x;
    float4* p = (float4*)(d + (size_t)row * SEQ);
    float4 v = p[threadIdx.x];
    float m = fmaxf(fmaxf(v.x, v.y), fmaxf(v.z, v.w));
#pragma unroll
    for (int o = 16; o; o >>= 1) m = fmaxf(m, __shfl_xor_sync(0xffffffffu, m, o));
    __shared__ float sm[32];
    const int w = threadIdx.x >> 5, l = threadIdx.x & 31;
    if (l == 0) sm[w] = m;
    __syncthreads();
    m = sm[0];
#pragma unroll
    for (int i = 1; i < 32; i++) m = fmaxf(m, sm[i]);
    __syncthreads();
    float4 e;
    e.x = expf(v.x - m); e.y = expf(v.y - m);
    e.z = expf(v.z - m); e.w = expf(v.w - m);
    float s = e.x + e.y + e.z + e.w;
#pragma unroll
    for (int o = 16; o; o >>= 1) s += __shfl_xor_sync(0xffffffffu, s, o);
    if (l == 0) sm[w] = s;
    __syncthreads();
    s = 0.f;
#pragma unroll
    for (int i = 0; i < 32; i++) s += sm[i];
    const float inv = 1.0f / s;
    e.x *= inv; e.y *= inv; e.z *= inv; e.w *= inv;
    p[threadIdx.x] = e;
}

// attn_out[b,n',c] = att[b, c/64, p(n')] * V[b, p(n'), c]; p(n')=(n'%128)*32+n'/128
__global__ __launch_bounds__(128) void gather_kernel(
    const __half* __restrict__ qkv, const float* __restrict__ att,
    __half* __restrict__ out)
{
    const int nb = blockIdx.x;
    const int b = nb >> 12, n = nb & 4095;
    const int pidx = (n & 127) * 32 + (n >> 7);
    const int t = threadIdx.x;                 // covers channels 8t..8t+7
    const float a = att[((size_t)(b * HEADS + (t >> 3))) * SEQ + pidx];
    const __half2* vv =
        (const __half2*)(qkv + ((size_t)((b << 12) + pidx)) * QKVW + 2 * DIM + 8 * t);
    __half2* o = (__half2*)(out + (size_t)nb * DIM + 8 * t);
#pragma unroll
    for (int i = 0; i < 4; i++) {
        const float2 v = __half22float2(vv[i]);
        o[i] = __floats2half2_rn(a * v.x, a * v.y);
    }
}

// ---------------------------------------------------------------------------
// Launch
// ---------------------------------------------------------------------------
extern "C" void kernel_launch(void* const* d_in, const int* in_sizes, int n_in,
                              void* d_out, int out_size)
{
    const float* x     = (const float*)d_in[0];
    const float* ln1_g = (const float*)d_in[1];
    const float* ln1_b = (const float*)d_in[2];
    const float* wq    = (const float*)d_in[3];
    const float* wk    = (const float*)d_in[4];
    const float* wv    = (const float*)d_in[5];
    const float* wo    = (const float*)d_in[6];
    const float* bo    = (const float*)d_in[7];
    const float* ln2_g = (const float*)d_in[8];
    const float* ln2_b = (const float*)d_in[9];
    const float* w1    = (const float*)d_in[10];
    const float* b1    = (const float*)d_in[11];
    const float* w2    = (const float*)d_in[12];
    const float* b2    = (const float*)d_in[13];
    float* out = (float*)d_out;

    __half *h1, *qkv, *ao, *h2, *act, *wqkvT, *woT, *w1T, *w2T;
    float *x2, *dots;
    cudaGetSymbolAddress((void**)&h1,   g_h1);
    cudaGetSymbolAddress((void**)&qkv,  g_qkv);
    cudaGetSymbolAddress((void**)&ao,   g_ao);
    cudaGetSymbolAddress((void**)&x2,   g_x2);
    cudaGetSymbolAddress((void**)&h2,   g_h2);
    cudaGetSymbolAddress((void**)&dots, g_dot);
    cudaGetSymbolAddress((void**)&act,  g_act);
    cudaGetSymbolAddress((void**)&wqkvT,g_wqkvT);
    cudaGetSymbolAddress((void**)&woT,  g_woT);
    cudaGetSymbolAddress((void**)&w1T,  g_w1T);
    cudaGetSymbolAddress((void**)&w2T,  g_w2T);

    cudaFuncSetAttribute(gemm_fp16<0>, cudaFuncAttributeMaxDynamicSharedMemorySize, SMEM_DYN);
    cudaFuncSetAttribute(gemm_fp16<1>, cudaFuncAttributeMaxDynamicSharedMemorySize, SMEM_DYN);
    cudaFuncSetAttribute(gemm_fp16<2>, cudaFuncAttributeMaxDynamicSharedMemorySize, SMEM_DYN);

    const dim3 tb(32, 8);
    // weight transposes -> fp16 K-major B operands
    transpose_k<<<dim3(32, 32), tb>>>(wq, wqkvT,                     DIM, DIM);
    transpose_k<<<dim3(32, 32), tb>>>(wk, wqkvT + (size_t)DIM*DIM,   DIM, DIM);
    transpose_k<<<dim3(32, 32), tb>>>(wv, wqkvT + (size_t)2*DIM*DIM, DIM, DIM);
    transpose_k<<<dim3(32, 32), tb>>>(wo, woT, DIM, DIM);
    transpose_k<<<dim3(128, 32), tb>>>(w1, w1T, DIM, DFF);
    transpose_k<<<dim3(32, 128), tb>>>(w2, w2T, DFF, DIM);

    // 1. h1 = LN1(x)  (fp16)
    ln_kernel<<<ROWS, 256>>>(x, ln1_g, ln1_b, h1);
    // 2. qkv = h1 @ [wq|wk|wv]  (fp16 out)
    gemm_fp16<0><<<dim3(QKVW/128, ROWS/128), 128, SMEM_DYN>>>(
        h1, wqkvT, qkv, nullptr, nullptr, ROWS, QKVW, DIM);
    // 3-5. diagonal dots -> softmax over sequence -> permuted gather * V
    dots_kernel<<<ROWS, 128>>>(qkv, dots);
    softmax_kernel<<<BATCH * HEADS, 1024>>>(dots);
    gather_kernel<<<ROWS, 128>>>(qkv, dots, ao);
    // 6. x2 = x + ao @ wo + bo  (fp32 out)
    gemm_fp16<1><<<dim3(DIM/128, ROWS/128), 128, SMEM_DYN>>>(
        ao, woT, x2, x, bo, ROWS, DIM, DIM);
    // 7. h2 = LN2(x2)  (fp16)
    ln_kernel<<<ROWS, 256>>>(x2, ln2_g, ln2_b, h2);
    // 8. act = gelu(h2 @ w1 + b1)  (fp16 out)
    gemm_fp16<2><<<dim3(DFF/128, ROWS/128), 128, SMEM_DYN>>>(
        h2, w1T, act, nullptr, b1, ROWS, DFF, DIM);
    // 9. out = x2 + act @ w2 + b2  (fp32 out)
    gemm_fp16<1><<<dim3(DIM/128, ROWS/128), 128, SMEM_DYN>>>(
        act, w2T, out, x2, b2, ROWS, DIM, DFF);
}

// round 5
// speedup vs baseline: 3.3203x; 1.2015x over previous
#include <cuda_runtime.h>
#include <cuda_fp16.h>
#include <math.h>
#include <stdint.h>

// Problem dims (fixed)
#define BATCH 4
#define SEQ   4096
#define DIM   1024
#define HEADS 16
#define DFF   4096
#define ROWS  16384
#define QKVW  3072

// ---------------------------------------------------------------------------
// Scratch (device globals; no runtime allocation allowed)
// ---------------------------------------------------------------------------
__device__ __half g_h1  [ROWS*(size_t)DIM];
__device__ __half g_qkv [ROWS*(size_t)QKVW];
__device__ __half g_ao  [ROWS*(size_t)DIM];
__device__ float  g_x2  [ROWS*(size_t)DIM];
__device__ __half g_h2  [ROWS*(size_t)DIM];
__device__ float  g_dot [BATCH*HEADS*(size_t)SEQ];
__device__ __half g_act [ROWS*(size_t)DFF];
__device__ __half g_wqkvT[(size_t)QKVW*DIM];   // [3072][1024] K-major (N rows)
__device__ __half g_woT [(size_t)DIM*DIM];
__device__ __half g_w1T [(size_t)DFF*DIM];
__device__ __half g_w2T [(size_t)DIM*DFF];

// ---------------------------------------------------------------------------
// Helpers
// ---------------------------------------------------------------------------
__device__ __forceinline__ float gelu_exact(float x) {
    return 0.5f * x * (1.0f + erff(x * 0.70710678118654752f));
}
__device__ __forceinline__ uint32_t smem_u32(const void* p) {
    uint32_t a;
    asm("{ .reg .u64 t; cvta.to.shared.u64 t, %1; cvt.u32.u64 %0, t; }"
        : "=r"(a) : "l"(p));
    return a;
}
__device__ __forceinline__ void cp16(uint32_t dst, const void* src) {
    asm volatile("cp.async.cg.shared.global [%0], [%1], 16;" :: "r"(dst), "l"(src));
}
__device__ __forceinline__ void cp_commit() {
    asm volatile("cp.async.commit_group;" ::: "memory");
}
#define LDMX4(r0, r1, r2, r3, addr)                                           \
    asm volatile("ldmatrix.sync.aligned.m8n8.x4.shared.b16 {%0,%1,%2,%3}, [%4];" \
        : "=r"(r0), "=r"(r1), "=r"(r2), "=r"(r3) : "r"(addr))

// smem row: 32 k-halves data + 8 pad halves -> stride 40 halves (80B).
// Rows r within an 8-row ldmatrix tile hit banks (r*20)%32: all distinct.
#define OP_B     10240                     // bytes per operand tile (128*80)
#define STAGE_B  (2*OP_B)                  // 20480
#define STAGES   4
#define SMEM_DYN (STAGES*STAGE_B)          // 81920

// ---------------------------------------------------------------------------
// FP16 tensor-core GEMM: C[M,N] = A[M,K] @ Bt[N,K]^T  (A,Bt fp16)
//  EPI 0: store half           (C = __half*)
//  EPI 1: float store +res+bias (C = float*, res fp32)
//  EPI 2: half store gelu(+bias)
// CTA 128x128, 128 threads (4 warps 2x2, warp tile 64x64), k-chunk 32,
// 4-stage cp.async pipeline, ldmatrix fragment loads.
// ---------------------------------------------------------------------------
template <int EPI>
__global__ __launch_bounds__(128, 2) void gemm_fp16(
    const __half* __restrict__ A, const __half* __restrict__ Bt,
    void* __restrict__ Cv, const float* __restrict__ res,
    const float* __restrict__ bias, int M, int N, int K)
{
    extern __shared__ char smc[];
    const uint32_t smb = smem_u32(smc);

    const int tid  = threadIdx.x;
    const int lane = tid & 31;
    const int wid  = tid >> 5;
    const int wm   = wid >> 1;
    const int wn   = wid & 1;
    const int g    = lane >> 2;
    const int t    = lane & 3;
    const int m0   = blockIdx.y << 7;
    const int n0   = blockIdx.x << 7;

    // ldmatrix per-lane base offsets (bytes within stage)
    // A tiles: lanes 0-7:(r,k0) 8-15:(r+8,k0) 16-23:(r,k8) 24-31:(r+8,k8)
    const uint32_t aoff =
        (uint32_t)(((wm * 64 + (lane & 7) + 8 * ((lane >> 3) & 1)) * 40 +
                    8 * (lane >> 4)) * 2);
    // B tiles: lanes 0-7:(n,k0) 8-15:(n,k8) 16-23:(n+8,k0) 24-31:(n+8,k8)
    const uint32_t boff =
        (uint32_t)(OP_B + (((wn * 64 + (lane & 7) + 8 * (lane >> 4)) * 40 +
                            8 * ((lane >> 3) & 1)) * 2));

    // staging: per operand 512 granules of 16B; 4 per thread
    uint32_t sA[4], sB[4];
    const __half* gA[4];
    const __half* gB[4];
#pragma unroll
    for (int j = 0; j < 4; j++) {
        const int gid = j * 128 + tid;
        const int row = gid >> 2, c = gid & 3;
        sA[j] = (uint32_t)(row * 80 + c * 16);
        sB[j] = (uint32_t)(OP_B + row * 80 + c * 16);
        gA[j] = A  + (size_t)(m0 + row) * K + c * 8;
        gB[j] = Bt + (size_t)(n0 + row) * K + c * 8;
    }

    float acc[4][8][4];
#pragma unroll
    for (int i = 0; i < 4; i++)
#pragma unroll
        for (int j = 0; j < 8; j++)
#pragma unroll
            for (int r = 0; r < 4; r++) acc[i][j][r] = 0.f;

    const int KT = K >> 5;

#pragma unroll
    for (int s = 0; s < STAGES; s++) {
        const uint32_t base = smb + s * STAGE_B;
        const int ko = s * 32;
#pragma unroll
        for (int j = 0; j < 4; j++) {
            cp16(base + sA[j], gA[j] + ko);
            cp16(base + sB[j], gB[j] + ko);
        }
        cp_commit();
    }

    for (int kt = 0; kt < KT; kt++) {
        asm volatile("cp.async.wait_group %0;" :: "n"(STAGES - 1) : "memory");
        __syncthreads();

        const uint32_t stg = smb + (kt % STAGES) * STAGE_B;

#pragma unroll
        for (int kc = 0; kc < 2; kc++) {
            const uint32_t kb = kc * 32;            // 16 halves
            uint32_t af[4][4];
#pragma unroll
            for (int i = 0; i < 4; i++)
                LDMX4(af[i][0], af[i][1], af[i][2], af[i][3],
                      stg + aoff + i * 1280 + kb);
            uint32_t bf[8][2];
#pragma unroll
            for (int jj = 0; jj < 4; jj++)
                LDMX4(bf[2 * jj][0], bf[2 * jj][1],
                      bf[2 * jj + 1][0], bf[2 * jj + 1][1],
                      stg + boff + jj * 1280 + kb);
#pragma unroll
            for (int i = 0; i < 4; i++)
#pragma unroll
                for (int j = 0; j < 8; j++) {
                    asm volatile(
                        "mma.sync.aligned.m16n8k16.row.col.f32.f16.f16.f32 "
                        "{%0,%1,%2,%3}, {%4,%5,%6,%7}, {%8,%9}, {%0,%1,%2,%3};"
                        : "+f"(acc[i][j][0]), "+f"(acc[i][j][1]),
                          "+f"(acc[i][j][2]), "+f"(acc[i][j][3])
                        : "r"(af[i][0]), "r"(af[i][1]),
                          "r"(af[i][2]), "r"(af[i][3]),
                          "r"(bf[j][0]), "r"(bf[j][1]));
                }
        }
        __syncthreads();

        const int nk = kt + STAGES;
        if (nk < KT) {
            const uint32_t base = smb + (nk % STAGES) * STAGE_B;
            const int ko = nk * 32;
#pragma unroll
            for (int j = 0; j < 4; j++) {
                cp16(base + sA[j], gA[j] + ko);
                cp16(base + sB[j], gB[j] + ko);
            }
        }
        cp_commit();
    }

    // epilogue
#pragma unroll
    for (int j = 0; j < 8; j++) {
        const int col = n0 + wn * 64 + j * 8 + t * 2;
        float2 bv = make_float2(0.f, 0.f);
        if (EPI != 0) bv = *(const float2*)&bias[col];
#pragma unroll
        for (int i = 0; i < 4; i++) {
            const int row0 = m0 + wm * 64 + i * 16 + g;
#pragma unroll
            for (int h = 0; h < 2; h++) {
                const int r = row0 + 8 * h;
                const float a = acc[i][j][2 * h + 0];
                const float b = acc[i][j][2 * h + 1];
                if (EPI == 0) {
                    *(__half2*)((__half*)Cv + (size_t)r * N + col) =
                        __floats2half2_rn(a, b);
                } else if (EPI == 1) {
                    const float2 rv = *(const float2*)&res[(size_t)r * N + col];
                    float2 o;
                    o.x = a + rv.x + bv.x;
                    o.y = b + rv.y + bv.y;
                    *(float2*)((float*)Cv + (size_t)r * N + col) = o;
                } else {
                    *(__half2*)((__half*)Cv + (size_t)r * N + col) =
                        __floats2half2_rn(gelu_exact(a + bv.x),
                                          gelu_exact(b + bv.y));
                }
            }
        }
    }
}

// ---------------------------------------------------------------------------
// Weight transpose: in fp32 [R][C] -> out fp16 [C][R]
// ---------------------------------------------------------------------------
__global__ __launch_bounds__(256) void transpose_k(
    const float* __restrict__ in, __half* __restrict__ out, int R, int C)
{
    __shared__ float t[32][33];
    const int c0 = blockIdx.x * 32, r0 = blockIdx.y * 32;
    const int tx = threadIdx.x, ty = threadIdx.y;
#pragma unroll
    for (int j = 0; j < 4; j++)
        t[ty + j * 8][tx] = in[(size_t)(r0 + ty + j * 8) * C + c0 + tx];
    __syncthreads();
#pragma unroll
    for (int j = 0; j < 4; j++)
        out[(size_t)(c0 + ty + j * 8) * R + r0 + tx] = __float2half(t[tx][ty + j * 8]);
}

// ---------------------------------------------------------------------------
// LayerNorm -> fp16 output (feeds GEMM A)
// ---------------------------------------------------------------------------
__global__ __launch_bounds__(256) void ln_kernel(
    const float* __restrict__ x, const float* __restrict__ gam,
    const float* __restrict__ bet, __half* __restrict__ out)
{
    const int row = blockIdx.x;
    const float* xr = x + (size_t)row * DIM;
    float v[4];
    float s = 0.f, ss = 0.f;
#pragma unroll
    for (int i = 0; i < 4; i++) {
        v[i] = xr[threadIdx.x + i * 256];
        s += v[i]; ss += v[i] * v[i];
    }
#pragma unroll
    for (int o = 16; o; o >>= 1) {
        s  += __shfl_xor_sync(0xffffffffu, s, o);
        ss += __shfl_xor_sync(0xffffffffu, ss, o);
    }
    __shared__ float sh1[8], sh2[8];
    const int w = threadIdx.x >> 5, l = threadIdx.x & 31;
    if (l == 0) { sh1[w] = s; sh2[w] = ss; }
    __syncthreads();
    s = 0.f; ss = 0.f;
#pragma unroll
    for (int i = 0; i < 8; i++) { s += sh1[i]; ss += sh2[i]; }
    const float mu   = s * (1.0f / DIM);
    const float var  = ss * (1.0f / DIM) - mu * mu;
    const float rstd = rsqrtf(var + 1e-5f);
    __half* outr = out + (size_t)row * DIM;
#pragma unroll
    for (int i = 0; i < 4; i++) {
        int c = threadIdx.x + i * 256;
        outr[c] = __float2half((v[i] - mu) * rstd * gam[c] + bet[c]);
    }
}

// ---------------------------------------------------------------------------
// Per-position head dots from fp16 qkv: thread t covers 8 channels
// ---------------------------------------------------------------------------
__global__ __launch_bounds__(128) void dots_kernel(
    const __half* __restrict__ qkv, float* __restrict__ dots)
{
    const int row = blockIdx.x;
    const int b = row >> 12, r = row & 4095;
    const int t = threadIdx.x;
    const __half2* qr = (const __half2*)(qkv + (size_t)row * QKVW + 8 * t);
    const __half2* kr = (const __half2*)(qkv + (size_t)row * QKVW + DIM + 8 * t);
    float p = 0.f;
#pragma unroll
    for (int i = 0; i < 4; i++) {
        const float2 a = __half22float2(qr[i]);
        const float2 c = __half22float2(kr[i]);
        p += a.x * c.x + a.y * c.y;
    }
#pragma unroll
    for (int o = 4; o; o >>= 1) p += __shfl_xor_sync(0xffffffffu, p, o);
    if ((t & 7) == 0)
        dots[((size_t)(b * HEADS + (t >> 3))) * SEQ + r] = p * 0.125f;
}

__global__ __launch_bounds__(1024) void softmax_kernel(float* __restrict__ d)
{
    const int row = blockIdx.x;
    float4* p = (float4*)(d + (size_t)row * SEQ);
    float4 v = p[threadIdx.x];
    float m = fmaxf(fmaxf(v.x, v.y), fmaxf(v.z, v.w));
#pragma unroll
    for (int o = 16; o; o >>= 1) m = fmaxf(m, __shfl_xor_sync(0xffffffffu, m, o));
    __shared__ float sm[32];
    const int w = threadIdx.x >> 5, l = threadIdx.x & 31;
    if (l == 0) sm[w] = m;
    __syncthreads();
    m = sm[0];
#pragma unroll
    for (int i = 1; i < 32; i++) m = fmaxf(m, sm[i]);
    __syncthreads();
    float4 e;
    e.x = expf(v.x - m); e.y = expf(v.y - m);
    e.z = expf(v.z - m); e.w = expf(v.w - m);
    float s = e.x + e.y + e.z + e.w;
#pragma unroll
    for (int o = 16; o; o >>= 1) s += __shfl_xor_sync(0xffffffffu, s, o);
    if (l == 0) sm[w] = s;
    __syncthreads();
    s = 0.f;
#pragma unroll
    for (int i = 0; i < 32; i++) s += sm[i];
    const float inv = 1.0f / s;
    e.x *= inv; e.y *= inv; e.z *= inv; e.w *= inv;
    p[threadIdx.x] = e;
}

// attn_out[b,n',c] = att[b, c/64, p(n')] * V[b, p(n'), c]; p(n')=(n'%128)*32+n'/128
__global__ __launch_bounds__(128) void gather_kernel(
    const __half* __restrict__ qkv, const float* __restrict__ att,
    __half* __restrict__ out)
{
    const int nb = blockIdx.x;
    const int b = nb >> 12, n = nb & 4095;
    const int pidx = (n & 127) * 32 + (n >> 7);
    const int t = threadIdx.x;                 // covers channels 8t..8t+7
    const float a = att[((size_t)(b * HEADS + (t >> 3))) * SEQ + pidx];
    const __half2* vv =
        (const __half2*)(qkv + ((size_t)((b << 12) + pidx)) * QKVW + 2 * DIM + 8 * t);
    __half2* o = (__half2*)(out + (size_t)nb * DIM + 8 * t);
#pragma unroll
    for (int i = 0; i < 4; i++) {
        const float2 v = __half22float2(vv[i]);
        o[i] = __floats2half2_rn(a * v.x, a * v.y);
    }
}

// ---------------------------------------------------------------------------
// Launch
// ---------------------------------------------------------------------------
extern "C" void kernel_launch(void* const* d_in, const int* in_sizes, int n_in,
                              void* d_out, int out_size)
{
    const float* x     = (const float*)d_in[0];
    const float* ln1_g = (const float*)d_in[1];
    const float* ln1_b = (const float*)d_in[2];
    const float* wq    = (const float*)d_in[3];
    const float* wk    = (const float*)d_in[4];
    const float* wv    = (const float*)d_in[5];
    const float* wo    = (const float*)d_in[6];
    const float* bo    = (const float*)d_in[7];
    const float* ln2_g = (const float*)d_in[8];
    const float* ln2_b = (const float*)d_in[9];
    const float* w1    = (const float*)d_in[10];
    const float* b1    = (const float*)d_in[11];
    const float* w2    = (const float*)d_in[12];
    const float* b2    = (const float*)d_in[13];
    float* out = (float*)d_out;

    __half *h1, *qkv, *ao, *h2, *act, *wqkvT, *woT, *w1T, *w2T;
    float *x2, *dots;
    cudaGetSymbolAddress((void**)&h1,   g_h1);
    cudaGetSymbolAddress((void**)&qkv,  g_qkv);
    cudaGetSymbolAddress((void**)&ao,   g_ao);
    cudaGetSymbolAddress((void**)&x2,   g_x2);
    cudaGetSymbolAddress((void**)&h2,   g_h2);
    cudaGetSymbolAddress((void**)&dots, g_dot);
    cudaGetSymbolAddress((void**)&act,  g_act);
    cudaGetSymbolAddress((void**)&wqkvT,g_wqkvT);
    cudaGetSymbolAddress((void**)&woT,  g_woT);
    cudaGetSymbolAddress((void**)&w1T,  g_w1T);
    cudaGetSymbolAddress((void**)&w2T,  g_w2T);

    cudaFuncSetAttribute(gemm_fp16<0>, cudaFuncAttributeMaxDynamicSharedMemorySize, SMEM_DYN);
    cudaFuncSetAttribute(gemm_fp16<1>, cudaFuncAttributeMaxDynamicSharedMemorySize, SMEM_DYN);
    cudaFuncSetAttribute(gemm_fp16<2>, cudaFuncAttributeMaxDynamicSharedMemorySize, SMEM_DYN);

    const dim3 tb(32, 8);
    // weight transposes -> fp16 K-major B operands
    transpose_k<<<dim3(32, 32), tb>>>(wq, wqkvT,                     DIM, DIM);
    transpose_k<<<dim3(32, 32), tb>>>(wk, wqkvT + (size_t)DIM*DIM,   DIM, DIM);
    transpose_k<<<dim3(32, 32), tb>>>(wv, wqkvT + (size_t)2*DIM*DIM, DIM, DIM);
    transpose_k<<<dim3(32, 32), tb>>>(wo, woT, DIM, DIM);
    transpose_k<<<dim3(128, 32), tb>>>(w1, w1T, DIM, DFF);
    transpose_k<<<dim3(32, 128), tb>>>(w2, w2T, DFF, DIM);

    // 1. h1 = LN1(x)  (fp16)
    ln_kernel<<<ROWS, 256>>>(x, ln1_g, ln1_b, h1);
    // 2. qkv = h1 @ [wq|wk|wv]  (fp16 out)
    gemm_fp16<0><<<dim3(QKVW/128, ROWS/128), 128, SMEM_DYN>>>(
        h1, wqkvT, qkv, nullptr, nullptr, ROWS, QKVW, DIM);
    // 3-5. diagonal dots -> softmax over sequence -> permuted gather * V
    dots_kernel<<<ROWS, 128>>>(qkv, dots);
    softmax_kernel<<<BATCH * HEADS, 1024>>>(dots);
    gather_kernel<<<ROWS, 128>>>(qkv, dots, ao);
    // 6. x2 = x + ao @ wo + bo  (fp32 out)
    gemm_fp16<1><<<dim3(DIM/128, ROWS/128), 128, SMEM_DYN>>>(
        ao, woT, x2, x, bo, ROWS, DIM, DIM);
    // 7. h2 = LN2(x2)  (fp16)
    ln_kernel<<<ROWS, 256>>>(x2, ln2_g, ln2_b, h2);
    // 8. act = gelu(h2 @ w1 + b1)  (fp16 out)
    gemm_fp16<2><<<dim3(DFF/128, ROWS/128), 128, SMEM_DYN>>>(
        h2, w1T, act, nullptr, b1, ROWS, DFF, DIM);
    // 9. out = x2 + act @ w2 + b2  (fp32 out)
    gemm_fp16<1><<<dim3(DIM/128, ROWS/128), 128, SMEM_DYN>>>(
        act, w2T, out, x2, b2, ROWS, DIM, DFF);
}